// round 3
// baseline (speedup 1.0000x reference)
#include <cuda_runtime.h>

#define NG 8
#define NT 2048
#define NH 2048
#define NE 8
#define CAP 320

#define NTOK (NG * NT)                 // 16384
#define OFF_PMAX   (NTOK * NE)         // 131072
#define OFF_LOGITS (OFF_PMAX + NTOK)   // 147456

#define TPW 8                          // tokens per warp
#define BLOCKS_PER_GROUP 64            // 2048 tokens / (4 warps * 8 tok)

typedef unsigned long long u64;

__device__ int g_expert_id[NTOK];
__device__ unsigned g_ctr[NG];         // monotonically increasing across launches

__device__ __forceinline__ u64 pack2(float a, float b) {
    u64 r;
    asm("mov.b64 %0, {%1, %2};" : "=l"(r) : "f"(a), "f"(b));
    return r;
}
__device__ __forceinline__ void unpack2(u64 v, float& a, float& b) {
    asm("mov.b64 {%0, %1}, %2;" : "=f"(a), "=f"(b) : "l"(v));
}
__device__ __forceinline__ void fma2(u64& d, u64 a, u64 b) {
    asm("fma.rn.f32x2 %0, %1, %2, %0;" : "+l"(d) : "l"(a), "l"(b));
}

// ---------------------------------------------------------------------------
// Fused kernel: router logits GEMV + softmax-max + argmax, then the last
// block of each group performs the capacity cumsum + one-hot write.
// ---------------------------------------------------------------------------
__global__ void __launch_bounds__(128, 3)
router_fused_kernel(const float* __restrict__ hs,
                    const float* __restrict__ W,
                    const float* __restrict__ bias,
                    float* __restrict__ out) {
    const int lane  = threadIdx.x & 31;
    const int gwarp = (blockIdx.x * blockDim.x + threadIdx.x) >> 5;
    const int t0    = gwarp * TPW;

    const float4* __restrict__ xb = (const float4*)hs + (size_t)t0 * (NH / 4);
    const float4* __restrict__ wv = (const float4*)W;   // [NE][512]

    // acc[tp][e]: f32x2 pair = (token 2tp, token 2tp+1) for expert e. 64 regs.
    u64 acc[4][NE];
#pragma unroll
    for (int tp = 0; tp < 4; ++tp)
#pragma unroll
        for (int e = 0; e < NE; ++e) acc[tp][e] = 0ull;

    for (int it = 0; it < NH / (32 * 4); ++it) {        // 16 iterations
        const int idx = it * 32 + lane;                 // float4 index in row

        u64 xq[4][4];                                   // [token-pair][h-sub]
#pragma unroll
        for (int tp = 0; tp < 4; ++tp) {
            float4 a = __ldg(xb + (2 * tp) * 512 + idx);
            float4 b = __ldg(xb + (2 * tp + 1) * 512 + idx);
            xq[tp][0] = pack2(a.x, b.x);
            xq[tp][1] = pack2(a.y, b.y);
            xq[tp][2] = pack2(a.z, b.z);
            xq[tp][3] = pack2(a.w, b.w);
        }
#pragma unroll
        for (int e = 0; e < NE; ++e) {
            float4 w = __ldg(wv + e * 512 + idx);
            u64 w0 = pack2(w.x, w.x), w1 = pack2(w.y, w.y);
            u64 w2 = pack2(w.z, w.z), w3 = pack2(w.w, w.w);
#pragma unroll
            for (int tp = 0; tp < 4; ++tp) {
                fma2(acc[tp][e], xq[tp][0], w0);
                fma2(acc[tp][e], xq[tp][1], w1);
                fma2(acc[tp][e], xq[tp][2], w2);
                fma2(acc[tp][e], xq[tp][3], w3);
            }
        }
    }

    // v[t*8 + e] per lane (partial sums over this lane's H slice)
    float v[64];
#pragma unroll
    for (int tp = 0; tp < 4; ++tp)
#pragma unroll
        for (int e = 0; e < NE; ++e) {
            float a, b;
            unpack2(acc[tp][e], a, b);
            v[(2 * tp) * 8 + e]     = a;
            v[(2 * tp + 1) * 8 + e] = b;
        }

    // 5-step butterfly: reduces across lanes while distributing results.
    // Final: lane holds totals for value indices {2*lane, 2*lane+1}.
#pragma unroll
    for (int s = 0; s < 5; ++s) {
        const int off  = 16 >> s;
        const int half = 32 >> s;
        const int sel  = (lane >> (4 - s)) & 1;
#pragma unroll
        for (int i = 0; i < half; ++i) {
            float a = v[i];
            float b = v[half + i];
            float mine = sel ? b : a;
            float send = sel ? a : b;
            float recv = __shfl_xor_sync(0xffffffffu, send, off);
            v[i] = mine + recv;
        }
    }

    const int t  = t0 + (lane >> 2);
    const int e0 = (lane & 3) * 2;
    const float2 bb = *(const float2*)(bias + e0);
    const float l0 = v[0] + bb.x;
    const float l1 = v[1] + bb.y;

    // coalesced logits store
    *(float2*)(out + OFF_LOGITS + (size_t)t0 * NE + 2 * lane) = make_float2(l0, l1);

    // max / argmax (first-max tie-break), softmax denominator
    float mx;
    int am;
    if (l1 > l0) { mx = l1; am = e0 + 1; } else { mx = l0; am = e0; }
#pragma unroll
    for (int off = 1; off <= 2; off <<= 1) {
        float omx = __shfl_xor_sync(0xffffffffu, mx, off);
        int   oam = __shfl_xor_sync(0xffffffffu, am, off);
        if (omx > mx || (omx == mx && oam < am)) { mx = omx; am = oam; }
    }
    float s = __expf(l0 - mx) + __expf(l1 - mx);
    s += __shfl_xor_sync(0xffffffffu, s, 1);
    s += __shfl_xor_sync(0xffffffffu, s, 2);

    if ((lane & 3) == 0) {
        out[OFF_PMAX + t] = 1.0f / s;
        g_expert_id[t] = am;
    }

    // ----------------- fused capacity scan (last block of group) ------------
    __shared__ int s_g;
    __syncthreads();                      // all warps' g_expert_id writes done
    if (threadIdx.x == 0) {
        __threadfence();                  // release our ids before signaling
        const int grp = (int)(blockIdx.x >> 6);   // 64 blocks per group
        unsigned old = atomicAdd(&g_ctr[grp], 1u);
        s_g = (((old + 1u) & 63u) == 0u) ? grp : -1;
    }
    __syncthreads();
    const int g = s_g;
    if (g < 0) return;
    __threadfence();                      // acquire all blocks' id writes

    const int tid = threadIdx.x;
    const int4* __restrict__ ids4 = (const int4*)(g_expert_id + g * NT);

    int myid[16];
    u64 c0 = 0ull, c1 = 0ull;
#pragma unroll
    for (int q = 0; q < 4; ++q) {
        int4 r = ids4[tid * 4 + q];
        myid[q * 4 + 0] = r.x; myid[q * 4 + 1] = r.y;
        myid[q * 4 + 2] = r.z; myid[q * 4 + 3] = r.w;
    }
#pragma unroll
    for (int i = 0; i < 16; ++i) {
        const int e = myid[i];
        if (e < 4) c0 += 1ull << (e * 16);
        else       c1 += 1ull << ((e - 4) * 16);
    }

    // block-wide Kogge-Stone inclusive scan over 128 threads
    __shared__ u64 sA[128], sB[128];
    u64 i0 = c0, i1 = c1;
    sA[tid] = i0; sB[tid] = i1;
    __syncthreads();
#pragma unroll
    for (int off = 1; off < 128; off <<= 1) {
        u64 a = 0ull, b = 0ull;
        if (tid >= off) { a = sA[tid - off]; b = sB[tid - off]; }
        __syncthreads();
        i0 += a; i1 += b;
        sA[tid] = i0; sB[tid] = i1;
        __syncthreads();
    }
    u64 r0 = i0 - c0, r1 = i1 - c1;       // exclusive prefix for this thread

    __shared__ unsigned char sflag[NT];   // eid (3b) | keep (bit 3)
#pragma unroll
    for (int i = 0; i < 16; ++i) {
        const int e = myid[i];
        int prio;
        if (e < 4) { r0 += 1ull << (e * 16);       prio = (int)((r0 >> (e * 16)) & 0xFFFF); }
        else       { r1 += 1ull << ((e - 4) * 16); prio = (int)((r1 >> ((e - 4) * 16)) & 0xFFFF); }
        sflag[tid * 16 + i] = (unsigned char)(e | ((prio <= CAP) ? 8 : 0));
    }
    __syncthreads();

    // coalesced one-hot write: each iteration, 128 threads write 128
    // consecutive float4 (half-token each)
    float4* __restrict__ dst = (float4*)out + (size_t)g * NT * 2;
    for (int k = tid; k < NT * 2; k += 128) {
        const int fl   = sflag[k >> 1];
        const int e    = fl & 7;
        const float kp = (fl & 8) ? 1.0f : 0.0f;
        const int rel  = e - (k & 1) * 4;
        float4 v4 = make_float4(0.f, 0.f, 0.f, 0.f);
        if (rel >= 0 && rel < 4) (&v4.x)[rel] = kp;
        dst[k] = v4;
    }
}

extern "C" void kernel_launch(void* const* d_in, const int* in_sizes, int n_in,
                              void* d_out, int out_size) {
    const float* hs   = (const float*)d_in[0];
    const float* W    = (const float*)d_in[1];
    const float* bias = (const float*)d_in[2];
    float* out = (float*)d_out;

    // 16384 tokens, 8 per warp, 4 warps per block -> 512 blocks
    router_fused_kernel<<<NTOK / (TPW * 4), 128>>>(hs, W, bias, out);
}

// round 4
// speedup vs baseline: 1.4683x; 1.4683x over previous
#include <cuda_runtime.h>

#define NG 8
#define NT 2048
#define NH 2048
#define NE 8
#define CAP 320

#define NTOK (NG * NT)                 // 16384
#define OFF_PMAX   (NTOK * NE)         // 131072
#define OFF_LOGITS (OFF_PMAX + NTOK)   // 147456

#define TPW 4                          // tokens per warp
#define THREADS 256                    // 8 warps -> 32 tokens per block
#define BLOCKS (NTOK / (TPW * 8))      // 512
#define BPG 64                         // blocks per group (2048/32)

typedef unsigned long long u64;

__device__ int g_expert_id[NTOK];
__device__ unsigned g_ctr[NG];         // monotone across graph replays

__device__ __forceinline__ u64 pack2(float a, float b) {
    u64 r;
    asm("mov.b64 %0, {%1, %2};" : "=l"(r) : "f"(a), "f"(b));
    return r;
}
__device__ __forceinline__ void unpack2(u64 v, float& a, float& b) {
    asm("mov.b64 {%0, %1}, %2;" : "=f"(a), "=f"(b) : "l"(v));
}
__device__ __forceinline__ void fma2(u64& d, u64 a, u64 b) {
    asm("fma.rn.f32x2 %0, %1, %2, %0;" : "+l"(d) : "l"(a), "l"(b));
}

extern __shared__ float4 sW[];         // [NE][NH/4] = 4096 float4 = 64KB

__global__ void __launch_bounds__(THREADS, 2)
router_fused_kernel(const float* __restrict__ hs,
                    const float* __restrict__ W,
                    const float* __restrict__ bias,
                    float* __restrict__ out) {
    const int tid  = threadIdx.x;
    const int lane = tid & 31;
    const int gwarp = (blockIdx.x * THREADS + tid) >> 5;
    const int t0    = gwarp * TPW;

    // stage W into shared memory (once per block)
    {
        const float4* __restrict__ wv = (const float4*)W;
#pragma unroll
        for (int k = 0; k < (NE * NH / 4) / THREADS; ++k)   // 16
            sW[tid + k * THREADS] = __ldg(wv + tid + k * THREADS);
    }
    __syncthreads();

    const float4* __restrict__ xb = (const float4*)hs + (size_t)t0 * (NH / 4);

    // acc[tok][e], f32x2 packed along H (lo = even pair, hi = odd pair)
    u64 acc[TPW][NE];
#pragma unroll
    for (int tk = 0; tk < TPW; ++tk)
#pragma unroll
        for (int e = 0; e < NE; ++e) acc[tk][e] = 0ull;

#pragma unroll 2
    for (int it = 0; it < NH / (32 * 4); ++it) {            // 16 iterations
        const int idx = it * 32 + lane;
        u64 xlo[TPW], xhi[TPW];
#pragma unroll
        for (int tk = 0; tk < TPW; ++tk) {
            float4 x = __ldg(xb + tk * (NH / 4) + idx);
            xlo[tk] = pack2(x.x, x.y);
            xhi[tk] = pack2(x.z, x.w);
        }
#pragma unroll
        for (int e = 0; e < NE; ++e) {
            float4 w = sW[e * (NH / 4) + idx];
            u64 wlo = pack2(w.x, w.y);
            u64 whi = pack2(w.z, w.w);
#pragma unroll
            for (int tk = 0; tk < TPW; ++tk) {
                fma2(acc[tk][e], xlo[tk], wlo);
                fma2(acc[tk][e], xhi[tk], whi);
            }
        }
    }

    // v[t*8+e]: 32 partial sums per lane
    float v[32];
#pragma unroll
    for (int tk = 0; tk < TPW; ++tk)
#pragma unroll
        for (int e = 0; e < NE; ++e) {
            float a, b;
            unpack2(acc[tk][e], a, b);
            v[tk * 8 + e] = a + b;
        }

    // 5-step butterfly: reduces across 32 lanes while distributing results.
    // Final: lane L holds the total for value index L (token L>>3, expert L&7).
#pragma unroll
    for (int s = 0; s < 5; ++s) {
        const int off  = 16 >> s;
        const int half = 16 >> s;
        const int sel  = (lane >> (4 - s)) & 1;
#pragma unroll
        for (int i = 0; i < half; ++i) {
            float a = v[i];
            float b = v[half + i];
            float mine = sel ? b : a;
            float send = sel ? a : b;
            float recv = __shfl_xor_sync(0xffffffffu, send, off);
            v[i] = mine + recv;
        }
    }

    const int e = lane & 7;
    const int t = t0 + (lane >> 3);
    const float l = v[0] + __ldg(bias + e);

    // fully coalesced logits store: 32 consecutive floats per warp
    out[OFF_LOGITS + (size_t)t0 * NE + lane] = l;

    // max/argmax (first-max tie-break) + softmax denom within 8-lane groups
    float mx = l;
    int am = e;
#pragma unroll
    for (int off = 1; off <= 4; off <<= 1) {
        float omx = __shfl_xor_sync(0xffffffffu, mx, off);
        int   oam = __shfl_xor_sync(0xffffffffu, am, off);
        if (omx > mx || (omx == mx && oam < am)) { mx = omx; am = oam; }
    }
    float s = __expf(l - mx);
#pragma unroll
    for (int off = 1; off <= 4; off <<= 1)
        s += __shfl_xor_sync(0xffffffffu, s, off);

    if (e == 0) {
        out[OFF_PMAX + t] = 1.0f / s;
        g_expert_id[t] = am;
    }

    // ----------------- fused capacity scan (last block of group) ------------
    __shared__ int s_g;
    __syncthreads();
    if (tid == 0) {
        __threadfence();                          // release our id writes
        const int grp = (int)(blockIdx.x / BPG);
        unsigned old = atomicAdd(&g_ctr[grp], 1u);
        s_g = (((old + 1u) & (BPG - 1u)) == 0u) ? grp : -1;
    }
    __syncthreads();
    const int g = s_g;
    if (g < 0) return;
    __threadfence();                              // acquire all id writes

    const int4* __restrict__ ids4 = (const int4*)(g_expert_id + g * NT);

    int myid[8];                                  // 2048 / 256 threads
    u64 c0 = 0ull, c1 = 0ull;
#pragma unroll
    for (int q = 0; q < 2; ++q) {
        int4 r = ids4[tid * 2 + q];
        myid[q * 4 + 0] = r.x; myid[q * 4 + 1] = r.y;
        myid[q * 4 + 2] = r.z; myid[q * 4 + 3] = r.w;
    }
#pragma unroll
    for (int i = 0; i < 8; ++i) {
        const int ee = myid[i];
        if (ee < 4) c0 += 1ull << (ee * 16);
        else        c1 += 1ull << ((ee - 4) * 16);
    }

    __shared__ u64 sA[THREADS], sB[THREADS];
    u64 i0 = c0, i1 = c1;
    sA[tid] = i0; sB[tid] = i1;
    __syncthreads();
#pragma unroll
    for (int off = 1; off < THREADS; off <<= 1) {
        u64 a = 0ull, b = 0ull;
        if (tid >= off) { a = sA[tid - off]; b = sB[tid - off]; }
        __syncthreads();
        i0 += a; i1 += b;
        sA[tid] = i0; sB[tid] = i1;
        __syncthreads();
    }
    u64 r0 = i0 - c0, r1 = i1 - c1;               // exclusive prefix

    __shared__ unsigned char sflag[NT];           // eid (3b) | keep (bit 3)
#pragma unroll
    for (int i = 0; i < 8; ++i) {
        const int ee = myid[i];
        int prio;
        if (ee < 4) { r0 += 1ull << (ee * 16);       prio = (int)((r0 >> (ee * 16)) & 0xFFFF); }
        else        { r1 += 1ull << ((ee - 4) * 16); prio = (int)((r1 >> ((ee - 4) * 16)) & 0xFFFF); }
        sflag[tid * 8 + i] = (unsigned char)(ee | ((prio <= CAP) ? 8 : 0));
    }
    __syncthreads();

    // coalesced one-hot write: 256 threads write consecutive float4
    float4* __restrict__ dst = (float4*)out + (size_t)g * NT * 2;
    for (int k = tid; k < NT * 2; k += THREADS) {
        const int fl   = sflag[k >> 1];
        const int ee   = fl & 7;
        const float kp = (fl & 8) ? 1.0f : 0.0f;
        const int rel  = ee - (k & 1) * 4;
        float4 v4 = make_float4(0.f, 0.f, 0.f, 0.f);
        if (rel >= 0 && rel < 4) (&v4.x)[rel] = kp;
        dst[k] = v4;
    }
}

extern "C" void kernel_launch(void* const* d_in, const int* in_sizes, int n_in,
                              void* d_out, int out_size) {
    const float* hs   = (const float*)d_in[0];
    const float* W    = (const float*)d_in[1];
    const float* bias = (const float*)d_in[2];
    float* out = (float*)d_out;

    static const int SMEM = NE * NH * (int)sizeof(float);   // 64KB dynamic
    cudaFuncSetAttribute(router_fused_kernel,
                         cudaFuncAttributeMaxDynamicSharedMemorySize, SMEM);
    router_fused_kernel<<<BLOCKS, THREADS, SMEM>>>(hs, W, bias, out);
}